// round 1
// baseline (speedup 1.0000x reference)
#include <cuda_runtime.h>
#include <cstdint>
#include <math.h>

#define BATCH 16
#define SEQT  256
#define VOCAB 32000
#define EMBD  200
#define HID   256
#define NT    (BATCH*SEQT)   // 4096 rows
#define G4    (4*HID)        // 1024 gate rows

// ---------------- scratch (static device arrays; no allocation) ----------------
__device__ float g_bufA[NT*HID];    // activations ping
__device__ float g_bufB[NT*HID];    // activations pong
__device__ float g_xg[NT*G4];       // per-layer input projections

// ---------------- helpers ----------------
__device__ __forceinline__ float sigmoid_f(float x) {
    x = fminf(fmaxf(x, -30.f), 30.f);
    return 1.f / (1.f + __expf(-x));
}
__device__ __forceinline__ float tanh_f(float x) {
    x = fminf(fmaxf(x, -15.f), 15.f);
    float e = __expf(2.f * x);
    return (e - 1.f) / (e + 1.f);
}
__device__ __forceinline__ uint32_t smem_u32(const void* p) {
    uint32_t a;
    asm("{ .reg .u64 t; cvta.to.shared.u64 t, %1; cvt.u32.u64 %0, t; }" : "=r"(a) : "l"(p));
    return a;
}

// ---------------- embedding gather ----------------
__global__ void embed_kernel(const int* __restrict__ x, const float* __restrict__ emb,
                             float* __restrict__ out) {
    int idx = blockIdx.x * blockDim.x + threadIdx.x;
    if (idx < NT * EMBD) {
        int n = idx / EMBD, e = idx - n * EMBD;
        out[(size_t)n * EMBD + e] = emb[(size_t)x[n] * EMBD + e];
    }
}

// ---------------- generic sgemm: out[n,m] = sum_c A[n,c]*W[m,c] + bias[m] ----------------
// BM=BN=128, BK=8, 256 threads, 8x8 per-thread tile. All dims here are multiples
// of the tiles (N=4096, M in {1024,32000}, C in {200,256}, C%8==0).
__global__ __launch_bounds__(256) void sgemm_nt(
    const float* __restrict__ A, int lda,
    const float* __restrict__ W, int ldw,
    float* __restrict__ Cout, int ldc,
    const float* __restrict__ bias, int Kc)
{
    __shared__ float As[8][128];
    __shared__ float Ws[8][128];

    const int tid  = threadIdx.x;
    const int row0 = blockIdx.y * 128;
    const int col0 = blockIdx.x * 128;
    const int tx = tid & 15;       // 0..15 (cols)
    const int ty = tid >> 4;       // 0..15 (rows)

    const int lr = tid >> 1;            // 0..127
    const int lc = (tid & 1) * 4;       // 0 or 4

    float acc[8][8];
#pragma unroll
    for (int i = 0; i < 8; i++)
#pragma unroll
        for (int j = 0; j < 8; j++) acc[i][j] = 0.f;

    for (int k0 = 0; k0 < Kc; k0 += 8) {
        float4 av = *(const float4*)&A[(size_t)(row0 + lr) * lda + k0 + lc];
        float4 wv = *(const float4*)&W[(size_t)(col0 + lr) * ldw + k0 + lc];
        As[lc + 0][lr] = av.x; As[lc + 1][lr] = av.y;
        As[lc + 2][lr] = av.z; As[lc + 3][lr] = av.w;
        Ws[lc + 0][lr] = wv.x; Ws[lc + 1][lr] = wv.y;
        Ws[lc + 2][lr] = wv.z; Ws[lc + 3][lr] = wv.w;
        __syncthreads();
#pragma unroll
        for (int c = 0; c < 8; c++) {
            float4 a0 = *(const float4*)&As[c][ty * 8];
            float4 a1 = *(const float4*)&As[c][ty * 8 + 4];
            float4 b0 = *(const float4*)&Ws[c][tx * 8];
            float4 b1 = *(const float4*)&Ws[c][tx * 8 + 4];
            float ar[8] = {a0.x,a0.y,a0.z,a0.w,a1.x,a1.y,a1.z,a1.w};
            float br[8] = {b0.x,b0.y,b0.z,b0.w,b1.x,b1.y,b1.z,b1.w};
#pragma unroll
            for (int i = 0; i < 8; i++)
#pragma unroll
                for (int j = 0; j < 8; j++) acc[i][j] += ar[i] * br[j];
        }
        __syncthreads();
    }

    float bb[8];
#pragma unroll
    for (int j = 0; j < 8; j++) bb[j] = bias[col0 + tx * 8 + j];

#pragma unroll
    for (int i = 0; i < 8; i++) {
        float* orow = &Cout[(size_t)(row0 + ty * 8 + i) * ldc + col0 + tx * 8];
        float4 v0, v1;
        v0.x = acc[i][0] + bb[0]; v0.y = acc[i][1] + bb[1];
        v0.z = acc[i][2] + bb[2]; v0.w = acc[i][3] + bb[3];
        v1.x = acc[i][4] + bb[4]; v1.y = acc[i][5] + bb[5];
        v1.z = acc[i][6] + bb[6]; v1.w = acc[i][7] + bb[7];
        *(float4*)&orow[0] = v0;
        *(float4*)&orow[4] = v1;
    }
}

// ---------------- LSTM recurrence: cluster of 8 CTAs per batch ----------------
// Each CTA owns gate rows { q*256 + rank*32 + jj : q in 0..3, jj in 0..31 } (128 rows),
// weights register-resident (thread (g,p) holds Wh[row, p*64 .. p*64+63]).
// h exchanged each step via st.shared::cluster pushes + barrier.cluster.
__global__ void __cluster_dims__(8, 1, 1) __launch_bounds__(512, 1)
lstm_rec(const float* __restrict__ xg, const float* __restrict__ Wh,
         float* __restrict__ hout)
{
    uint32_t rank;
    asm("mov.u32 %0, %%cluster_ctarank;" : "=r"(rank));
    const int batch = blockIdx.x >> 3;
    const int tid = threadIdx.x;
    const int g = tid >> 2;     // 0..127 local gate
    const int p = tid & 3;      // 0..3 k-partition
    const int q = g >> 5;       // gate type i,f,g,o
    const int jj = g & 31;
    const int row = q * 256 + (int)rank * 32 + jj;   // global gate row

    // register-resident weight slice: Wh[row, p*64 .. p*64+63]
    float4 w[16];
    const float4* wrow = (const float4*)(Wh + (size_t)row * HID + p * 64);
#pragma unroll
    for (int i = 0; i < 16; i++) w[i] = wrow[i];

    __shared__ float h_sh[2][HID];
    __shared__ float g_sh[128];

    for (int i = tid; i < 2 * HID; i += 512) (&h_sh[0][0])[i] = 0.f;
    float c_reg = 0.f;
    __syncthreads();
    // initial cluster barrier: peers' h_sh must be zeroed before anyone pushes
    asm volatile("barrier.cluster.arrive.aligned;" ::: "memory");
    asm volatile("barrier.cluster.wait.aligned;" ::: "memory");

    const float* xg_b = xg + (size_t)batch * SEQT * G4;
    float* ho_b = hout + (size_t)batch * SEQT * HID;

    int cur = 0;
    for (int t = 0; t < SEQT; t++) {
        // partial dot over this thread's 64 k's
        float acc = 0.f;
        const float4* hv = (const float4*)&h_sh[cur][p * 64];
#pragma unroll
        for (int i = 0; i < 16; i++) {
            float4 h4 = hv[i];
            acc += w[i].x * h4.x + w[i].y * h4.y + w[i].z * h4.z + w[i].w * h4.w;
        }
        acc += __shfl_down_sync(0xFFFFFFFFu, acc, 2, 4);
        acc += __shfl_down_sync(0xFFFFFFFFu, acc, 1, 4);
        if (p == 0) g_sh[g] = acc + xg_b[(size_t)t * G4 + row];
        __syncthreads();

        // activations spread over 4 warps
        if (tid < 128) {
            float v = g_sh[tid];
            g_sh[tid] = (tid >= 64 && tid < 96) ? tanh_f(v) : sigmoid_f(v);
        }
        __syncthreads();

        if (tid < 32) {
            float i_ = g_sh[tid], f_ = g_sh[32 + tid];
            float gg = g_sh[64 + tid], o_ = g_sh[96 + tid];
            c_reg = f_ * c_reg + i_ * gg;
            float h = o_ * tanh_f(c_reg);
            int j = (int)rank * 32 + tid;
            int nxt = cur ^ 1;
            h_sh[nxt][j] = h;
            uint32_t laddr = smem_u32(&h_sh[nxt][j]);
#pragma unroll
            for (int pr = 0; pr < 8; pr++) {
                if (pr == (int)rank) continue;
                uint32_t raddr;
                asm("mapa.shared::cluster.u32 %0, %1, %2;" : "=r"(raddr) : "r"(laddr), "r"(pr));
                asm volatile("st.shared::cluster.f32 [%0], %1;" :: "r"(raddr), "f"(h) : "memory");
            }
            ho_b[(size_t)t * HID + j] = h;
        }
        // one cluster barrier per step (also a full block barrier)
        asm volatile("barrier.cluster.arrive.aligned;" ::: "memory");
        asm volatile("barrier.cluster.wait.aligned;" ::: "memory");
        cur ^= 1;
    }
}

// ---------------- in-place log_softmax over rows of V ----------------
__global__ __launch_bounds__(256) void logsoftmax_kernel(float* __restrict__ out) {
    const int n = blockIdx.x;
    float* row = out + (size_t)n * VOCAB;
    const int tid = threadIdx.x;
    __shared__ float red[8];
    __shared__ float bval;

    float m = -1e30f;
    for (int k = tid; k < VOCAB; k += 256) m = fmaxf(m, row[k]);
#pragma unroll
    for (int o = 16; o; o >>= 1) m = fmaxf(m, __shfl_xor_sync(0xFFFFFFFFu, m, o));
    if ((tid & 31) == 0) red[tid >> 5] = m;
    __syncthreads();
    if (tid == 0) {
        float mm = red[0];
#pragma unroll
        for (int i = 1; i < 8; i++) mm = fmaxf(mm, red[i]);
        bval = mm;
    }
    __syncthreads();
    const float rowmax = bval;
    __syncthreads();

    float s = 0.f;
    for (int k = tid; k < VOCAB; k += 256) s += __expf(row[k] - rowmax);
#pragma unroll
    for (int o = 16; o; o >>= 1) s += __shfl_xor_sync(0xFFFFFFFFu, s, o);
    if ((tid & 31) == 0) red[tid >> 5] = s;
    __syncthreads();
    if (tid == 0) {
        float ss = 0.f;
#pragma unroll
        for (int i = 0; i < 8; i++) ss += red[i];
        bval = rowmax + logf(ss);
    }
    __syncthreads();
    const float lse = bval;
    for (int k = tid; k < VOCAB; k += 256) row[k] = row[k] - lse;
}

// ---------------- launch ----------------
extern "C" void kernel_launch(void* const* d_in, const int* in_sizes, int n_in,
                              void* d_out, int out_size) {
    (void)in_sizes; (void)n_in; (void)out_size;
    const int*   x   = (const int*)d_in[0];
    const float* emb = (const float*)d_in[1];
    const float* Wi[3] = {(const float*)d_in[2], (const float*)d_in[5], (const float*)d_in[8]};
    const float* Wh[3] = {(const float*)d_in[3], (const float*)d_in[6], (const float*)d_in[9]};
    const float* bs[3] = {(const float*)d_in[4], (const float*)d_in[7], (const float*)d_in[10]};
    const float* fcW = (const float*)d_in[11];
    const float* fcb = (const float*)d_in[12];
    float* out = (float*)d_out;

    float *bufA, *bufB, *xg;
    cudaGetSymbolAddress((void**)&bufA, g_bufA);
    cudaGetSymbolAddress((void**)&bufB, g_bufB);
    cudaGetSymbolAddress((void**)&xg,   g_xg);

    embed_kernel<<<(NT * EMBD + 255) / 256, 256>>>(x, emb, bufA);

    // layer 0: input proj (C=200) then recurrence
    sgemm_nt<<<dim3(G4 / 128, NT / 128), 256>>>(bufA, EMBD, Wi[0], EMBD, xg, G4, bs[0], EMBD);
    lstm_rec<<<BATCH * 8, 512>>>(xg, Wh[0], bufB);

    // layer 1
    sgemm_nt<<<dim3(G4 / 128, NT / 128), 256>>>(bufB, HID, Wi[1], HID, xg, G4, bs[1], HID);
    lstm_rec<<<BATCH * 8, 512>>>(xg, Wh[1], bufA);

    // layer 2
    sgemm_nt<<<dim3(G4 / 128, NT / 128), 256>>>(bufA, HID, Wi[2], HID, xg, G4, bs[2], HID);
    lstm_rec<<<BATCH * 8, 512>>>(xg, Wh[2], bufB);

    // FC into d_out, then in-place log_softmax
    sgemm_nt<<<dim3(VOCAB / 128, NT / 128), 256>>>(bufB, HID, fcW, HID, out, VOCAB, fcb, HID);
    logsoftmax_kernel<<<NT, 256>>>(out);
}

// round 3
// speedup vs baseline: 1.2346x; 1.2346x over previous
#include <cuda_runtime.h>
#include <cuda_bf16.h>
#include <cstdint>
#include <math.h>

#define BATCH 16
#define SEQT  256
#define VOCAB 32000
#define EMBD  200
#define HID   256
#define NT    (BATCH*SEQT)   // 4096 rows
#define G4    (4*HID)        // 1024 gate rows

// ---------------- scratch (static device arrays; no allocation) ----------------
__device__ float g_bufA[NT*HID];
__device__ float g_bufB[NT*HID];
__device__ float g_xg[NT*G4];
__device__ __align__(16) __nv_bfloat16 g_hb[NT*HID];      // bf16 activations for FC
__device__ __align__(16) __nv_bfloat16 g_wb[VOCAB*HID];   // bf16 fcW

// ---------------- helpers ----------------
__device__ __forceinline__ float sigmoid_f(float x) {
    x = fminf(fmaxf(x, -30.f), 30.f);
    return 1.f / (1.f + __expf(-x));
}
__device__ __forceinline__ float tanh_f(float x) {
    x = fminf(fmaxf(x, -15.f), 15.f);
    float e = __expf(2.f * x);
    return (e - 1.f) / (e + 1.f);
}
__device__ __forceinline__ uint32_t smem_u32(const void* p) {
    uint32_t a;
    asm("{ .reg .u64 t; cvta.to.shared.u64 t, %1; cvt.u32.u64 %0, t; }" : "=r"(a) : "l"(p));
    return a;
}

// ---------------- embedding gather ----------------
__global__ void embed_kernel(const int* __restrict__ x, const float* __restrict__ emb,
                             float* __restrict__ out) {
    int idx = blockIdx.x * blockDim.x + threadIdx.x;
    if (idx < NT * EMBD) {
        int n = idx / EMBD, e = idx - n * EMBD;
        out[(size_t)n * EMBD + e] = emb[(size_t)x[n] * EMBD + e];
    }
}

// ---------------- fp32 -> bf16 cast (n divisible by 4) ----------------
__global__ void cast_f2bf(const float* __restrict__ in, __nv_bfloat16* __restrict__ out, int n4) {
    int i = blockIdx.x * blockDim.x + threadIdx.x;
    if (i < n4) {
        float4 v = ((const float4*)in)[i];
        __nv_bfloat162 a = __floats2bfloat162_rn(v.x, v.y);
        __nv_bfloat162 b = __floats2bfloat162_rn(v.z, v.w);
        ((uint2*)out)[i] = make_uint2(*(uint32_t*)&a, *(uint32_t*)&b);
    }
}

// ---------------- generic fp32 sgemm (input projections, kept fp32 for accuracy) ----------------
__global__ __launch_bounds__(256) void sgemm_nt(
    const float* __restrict__ A, int lda,
    const float* __restrict__ W, int ldw,
    float* __restrict__ Cout, int ldc,
    const float* __restrict__ bias, int Kc)
{
    __shared__ float As[8][128];
    __shared__ float Ws[8][128];

    const int tid  = threadIdx.x;
    const int row0 = blockIdx.y * 128;
    const int col0 = blockIdx.x * 128;
    const int tx = tid & 15;
    const int ty = tid >> 4;
    const int lr = tid >> 1;
    const int lc = (tid & 1) * 4;

    float acc[8][8];
#pragma unroll
    for (int i = 0; i < 8; i++)
#pragma unroll
        for (int j = 0; j < 8; j++) acc[i][j] = 0.f;

    for (int k0 = 0; k0 < Kc; k0 += 8) {
        float4 av = *(const float4*)&A[(size_t)(row0 + lr) * lda + k0 + lc];
        float4 wv = *(const float4*)&W[(size_t)(col0 + lr) * ldw + k0 + lc];
        As[lc + 0][lr] = av.x; As[lc + 1][lr] = av.y;
        As[lc + 2][lr] = av.z; As[lc + 3][lr] = av.w;
        Ws[lc + 0][lr] = wv.x; Ws[lc + 1][lr] = wv.y;
        Ws[lc + 2][lr] = wv.z; Ws[lc + 3][lr] = wv.w;
        __syncthreads();
#pragma unroll
        for (int c = 0; c < 8; c++) {
            float4 a0 = *(const float4*)&As[c][ty * 8];
            float4 a1 = *(const float4*)&As[c][ty * 8 + 4];
            float4 b0 = *(const float4*)&Ws[c][tx * 8];
            float4 b1 = *(const float4*)&Ws[c][tx * 8 + 4];
            float ar[8] = {a0.x,a0.y,a0.z,a0.w,a1.x,a1.y,a1.z,a1.w};
            float br[8] = {b0.x,b0.y,b0.z,b0.w,b1.x,b1.y,b1.z,b1.w};
#pragma unroll
            for (int i = 0; i < 8; i++)
#pragma unroll
                for (int j = 0; j < 8; j++) acc[i][j] += ar[i] * br[j];
        }
        __syncthreads();
    }

    float bb[8];
#pragma unroll
    for (int j = 0; j < 8; j++) bb[j] = bias[col0 + tx * 8 + j];

#pragma unroll
    for (int i = 0; i < 8; i++) {
        float* orow = &Cout[(size_t)(row0 + ty * 8 + i) * ldc + col0 + tx * 8];
        float4 v0, v1;
        v0.x = acc[i][0] + bb[0]; v0.y = acc[i][1] + bb[1];
        v0.z = acc[i][2] + bb[2]; v0.w = acc[i][3] + bb[3];
        v1.x = acc[i][4] + bb[4]; v1.y = acc[i][5] + bb[5];
        v1.z = acc[i][6] + bb[6]; v1.w = acc[i][7] + bb[7];
        *(float4*)&orow[0] = v0;
        *(float4*)&orow[4] = v1;
    }
}

// ---------------- LSTM recurrence: cluster of 8 CTAs per batch ----------------
__global__ void __cluster_dims__(8, 1, 1) __launch_bounds__(512, 1)
lstm_rec(const float* __restrict__ xg, const float* __restrict__ Wh,
         float* __restrict__ hout)
{
    uint32_t rank;
    asm("mov.u32 %0, %%cluster_ctarank;" : "=r"(rank));
    const int batch = blockIdx.x >> 3;
    const int tid = threadIdx.x;
    const int g = tid >> 2;
    const int p = tid & 3;
    const int q = g >> 5;
    const int jj = g & 31;
    const int row = q * 256 + (int)rank * 32 + jj;

    float4 w[16];
    const float4* wrow = (const float4*)(Wh + (size_t)row * HID + p * 64);
#pragma unroll
    for (int i = 0; i < 16; i++) w[i] = wrow[i];

    __shared__ float h_sh[2][HID];
    __shared__ float g_sh[128];

    for (int i = tid; i < 2 * HID; i += 512) (&h_sh[0][0])[i] = 0.f;
    float c_reg = 0.f;
    __syncthreads();
    asm volatile("barrier.cluster.arrive.aligned;" ::: "memory");
    asm volatile("barrier.cluster.wait.aligned;" ::: "memory");

    const float* xg_b = xg + (size_t)batch * SEQT * G4;
    float* ho_b = hout + (size_t)batch * SEQT * HID;

    int cur = 0;
    for (int t = 0; t < SEQT; t++) {
        float xgv = 0.f;
        if (p == 0) xgv = xg_b[(size_t)t * G4 + row];

        float a0 = 0.f, a1 = 0.f, a2 = 0.f, a3 = 0.f;
        const float4* hv = (const float4*)&h_sh[cur][p * 64];
#pragma unroll
        for (int i = 0; i < 16; i++) {
            float4 h4 = hv[i];
            a0 += w[i].x * h4.x; a1 += w[i].y * h4.y;
            a2 += w[i].z * h4.z; a3 += w[i].w * h4.w;
        }
        float acc = (a0 + a1) + (a2 + a3);
        acc += __shfl_down_sync(0xFFFFFFFFu, acc, 2, 4);
        acc += __shfl_down_sync(0xFFFFFFFFu, acc, 1, 4);
        if (p == 0) g_sh[g] = acc + xgv;
        __syncthreads();

        if (tid < 32) {
            float i_ = sigmoid_f(g_sh[tid]);
            float f_ = sigmoid_f(g_sh[32 + tid]);
            float gg = tanh_f(g_sh[64 + tid]);
            float o_ = sigmoid_f(g_sh[96 + tid]);
            c_reg = f_ * c_reg + i_ * gg;
            float h = o_ * tanh_f(c_reg);
            int j = (int)rank * 32 + tid;
            int nxt = cur ^ 1;
            h_sh[nxt][j] = h;
            uint32_t laddr = smem_u32(&h_sh[nxt][j]);
#pragma unroll
            for (int pr = 0; pr < 8; pr++) {
                if (pr == (int)rank) continue;
                uint32_t raddr;
                asm("mapa.shared::cluster.u32 %0, %1, %2;" : "=r"(raddr) : "r"(laddr), "r"(pr));
                asm volatile("st.shared::cluster.f32 [%0], %1;" :: "r"(raddr), "f"(h) : "memory");
            }
            ho_b[(size_t)t * HID + j] = h;
        }
        asm volatile("barrier.cluster.arrive.aligned;" ::: "memory");
        asm volatile("barrier.cluster.wait.aligned;" ::: "memory");
        cur ^= 1;
    }
}

// ---------------- FC GEMM via warp-level bf16 mma.sync ----------------
// CTA tile 128(M) x 128(N), K=256 resident in smem. 8 warps, each 64x32.
// smem: A 64KB @0, B 64KB @65536, XOR-swizzled 16B chunks, pitch 512B.
#define FC_SMEM_BYTES (128*512*2)

__device__ __forceinline__ void ldsm_x4(uint32_t addr, uint32_t& r0, uint32_t& r1,
                                        uint32_t& r2, uint32_t& r3) {
    asm volatile("ldmatrix.sync.aligned.m8n8.x4.shared.b16 {%0,%1,%2,%3}, [%4];"
                 : "=r"(r0), "=r"(r1), "=r"(r2), "=r"(r3) : "r"(addr));
}
__device__ __forceinline__ void mma16816(float* c, const uint32_t* a, const uint32_t* b) {
    asm volatile("mma.sync.aligned.m16n8k16.row.col.f32.bf16.bf16.f32 "
                 "{%0,%1,%2,%3}, {%4,%5,%6,%7}, {%8,%9}, {%0,%1,%2,%3};"
                 : "+f"(c[0]), "+f"(c[1]), "+f"(c[2]), "+f"(c[3])
                 : "r"(a[0]), "r"(a[1]), "r"(a[2]), "r"(a[3]), "r"(b[0]), "r"(b[1]));
}

__global__ __launch_bounds__(256, 1) void fc_mma(
    const __nv_bfloat16* __restrict__ Ab,   // [NT, 256]
    const __nv_bfloat16* __restrict__ Bb,   // [VOCAB, 256]
    const float* __restrict__ bias,         // [VOCAB]
    float* __restrict__ out)                // [NT, VOCAB]
{
    extern __shared__ __align__(128) unsigned char smem[];
    const uint32_t sbase = smem_u32(smem);
    const uint32_t sA = sbase;
    const uint32_t sB = sbase + 65536;

    const int tid = threadIdx.x;
    const int wid = tid >> 5;
    const int lid = tid & 31;
    const int row0 = blockIdx.x * 128;   // M block (fast-varying -> B tile L2 reuse)
    const int col0 = blockIdx.y * 128;   // vocab block

    // ---- load tiles: 16B chunk idx = row*32 + c ; phys = row*512 + (c^(row&7))*16
#pragma unroll
    for (int i = 0; i < 16; i++) {
        int idx = tid + i * 256;          // 0..4095
        int r = idx >> 5, c = idx & 31;
        uint32_t soff = (uint32_t)r * 512u + (uint32_t)((c ^ (r & 7)) << 4);
        *(uint4*)(smem + soff) = *(const uint4*)(Ab + (size_t)(row0 + r) * HID + (c << 3));
        *(uint4*)(smem + 65536 + soff) = *(const uint4*)(Bb + (size_t)(col0 + r) * HID + (c << 3));
    }
    __syncthreads();

    const int mw = (wid & 1) * 64;   // warp M offset
    const int nw = (wid >> 1) * 32;  // warp N offset

    float c[4][4][4];
#pragma unroll
    for (int mi = 0; mi < 4; mi++)
#pragma unroll
        for (int ni = 0; ni < 4; ni++)
#pragma unroll
            for (int e = 0; e < 4; e++) c[mi][ni][e] = 0.f;

#pragma unroll
    for (int ks = 0; ks < 16; ks++) {
        // A fragments: 4 m-tiles of 16
        uint32_t a[4][4];
#pragma unroll
        for (int mi = 0; mi < 4; mi++) {
            int r = mw + mi * 16 + (lid & 15);
            int chunk = ks * 2 + (lid >> 4);
            uint32_t addr = sA + (uint32_t)r * 512u + (uint32_t)((chunk ^ (r & 7)) << 4);
            ldsm_x4(addr, a[mi][0], a[mi][1], a[mi][2], a[mi][3]);
        }
        // B fragments: 4 n-tiles of 8 via 2 x4 loads
        uint32_t b[4][2];
#pragma unroll
        for (int nb = 0; nb < 2; nb++) {
            int n = nw + nb * 16 + (lid & 7) + ((lid & 16) ? 8 : 0);
            int chunk = ks * 2 + ((lid & 8) ? 1 : 0);
            uint32_t addr = sB + (uint32_t)n * 512u + (uint32_t)((chunk ^ (n & 7)) << 4);
            uint32_t r0, r1, r2, r3;
            ldsm_x4(addr, r0, r1, r2, r3);
            b[nb * 2 + 0][0] = r0; b[nb * 2 + 0][1] = r1;
            b[nb * 2 + 1][0] = r2; b[nb * 2 + 1][1] = r3;
        }
#pragma unroll
        for (int mi = 0; mi < 4; mi++)
#pragma unroll
            for (int ni = 0; ni < 4; ni++)
                mma16816(c[mi][ni], a[mi], b[ni]);
    }

    // ---- epilogue: direct stores (float2), bias added
#pragma unroll
    for (int mi = 0; mi < 4; mi++) {
        int r = row0 + mw + mi * 16 + (lid >> 2);
#pragma unroll
        for (int ni = 0; ni < 4; ni++) {
            int col = col0 + nw + ni * 8 + (lid & 3) * 2;
            float2 bv = *(const float2*)&bias[col];
            float2 v0 = make_float2(c[mi][ni][0] + bv.x, c[mi][ni][1] + bv.y);
            float2 v1 = make_float2(c[mi][ni][2] + bv.x, c[mi][ni][3] + bv.y);
            *(float2*)&out[(size_t)r * VOCAB + col] = v0;
            *(float2*)&out[(size_t)(r + 8) * VOCAB + col] = v1;
        }
    }
}

// ---------------- online log_softmax (2 reads + 1 write) ----------------
__global__ __launch_bounds__(256) void logsoftmax_kernel(float* __restrict__ out) {
    const int n = blockIdx.x;
    float* row = out + (size_t)n * VOCAB;
    const int tid = threadIdx.x;
    __shared__ float redm[8], reds[8];
    __shared__ float bcast;

    float m = -1e30f, s = 0.f;
    for (int k = tid; k < VOCAB; k += 256) {
        float v = row[k];
        float M = fmaxf(m, v);
        s = s * __expf(m - M) + __expf(v - M);
        m = M;
    }
#pragma unroll
    for (int o = 16; o; o >>= 1) {
        float mo = __shfl_xor_sync(0xFFFFFFFFu, m, o);
        float so = __shfl_xor_sync(0xFFFFFFFFu, s, o);
        float M = fmaxf(m, mo);
        s = s * __expf(m - M) + so * __expf(mo - M);
        m = M;
    }
    if ((tid & 31) == 0) { redm[tid >> 5] = m; reds[tid >> 5] = s; }
    __syncthreads();
    if (tid == 0) {
        float M = redm[0], S = reds[0];
#pragma unroll
        for (int i = 1; i < 8; i++) {
            float M2 = fmaxf(M, redm[i]);
            S = S * __expf(M - M2) + reds[i] * __expf(redm[i] - M2);
            M = M2;
        }
        bcast = M + logf(S);
    }
    __syncthreads();
    const float lse = bcast;
    for (int k = tid; k < VOCAB; k += 256) row[k] = row[k] - lse;
}

// ---------------- launch ----------------
extern "C" void kernel_launch(void* const* d_in, const int* in_sizes, int n_in,
                              void* d_out, int out_size) {
    (void)in_sizes; (void)n_in; (void)out_size;
    const int*   x   = (const int*)d_in[0];
    const float* emb = (const float*)d_in[1];
    const float* Wi[3] = {(const float*)d_in[2], (const float*)d_in[5], (const float*)d_in[8]};
    const float* Wh[3] = {(const float*)d_in[3], (const float*)d_in[6], (const float*)d_in[9]};
    const float* bs[3] = {(const float*)d_in[4], (const float*)d_in[7], (const float*)d_in[10]};
    const float* fcW = (const float*)d_in[11];
    const float* fcb = (const float*)d_in[12];
    float* out = (float*)d_out;

    float *bufA, *bufB, *xg;
    __nv_bfloat16 *hb, *wb;
    cudaGetSymbolAddress((void**)&bufA, g_bufA);
    cudaGetSymbolAddress((void**)&bufB, g_bufB);
    cudaGetSymbolAddress((void**)&xg,   g_xg);
    cudaGetSymbolAddress((void**)&hb,   g_hb);
    cudaGetSymbolAddress((void**)&wb,   g_wb);

    cudaFuncSetAttribute(fc_mma, cudaFuncAttributeMaxDynamicSharedMemorySize, FC_SMEM_BYTES);

    // launch order arranged so ncu -s 5 captures lstm_rec (launch idx 5)
    embed_kernel<<<(NT * EMBD + 255) / 256, 256>>>(x, emb, bufA);                       // 0
    cast_f2bf<<<(VOCAB * HID / 4 + 255) / 256, 256>>>(fcW, wb, VOCAB * HID / 4);        // 1

    sgemm_nt<<<dim3(G4 / 128, NT / 128), 256>>>(bufA, EMBD, Wi[0], EMBD, xg, G4, bs[0], EMBD); // 2
    lstm_rec<<<BATCH * 8, 512>>>(xg, Wh[0], bufB);                                      // 3

    sgemm_nt<<<dim3(G4 / 128, NT / 128), 256>>>(bufB, HID, Wi[1], HID, xg, G4, bs[1], HID);    // 4
    lstm_rec<<<BATCH * 8, 512>>>(xg, Wh[1], bufA);                                      // 5  <- ncu

    sgemm_nt<<<dim3(G4 / 128, NT / 128), 256>>>(bufA, HID, Wi[2], HID, xg, G4, bs[2], HID);    // 6
    lstm_rec<<<BATCH * 8, 512>>>(xg, Wh[2], bufB);                                      // 7

    cast_f2bf<<<(NT * HID / 4 + 255) / 256, 256>>>(bufB, hb, NT * HID / 4);             // 8
    fc_mma<<<dim3(NT / 128, VOCAB / 128), 256, FC_SMEM_BYTES>>>(hb, wb, fcb, out);      // 9
    logsoftmax_kernel<<<NT, 256>>>(out);                                                // 10
}